// round 11
// baseline (speedup 1.0000x reference)
#include <cuda_runtime.h>

#define RB 64
#define CB 64
#define NROWS 8192
#define TCOLS 8192
#define T4 (TCOLS / 4)         // 2048 float4 per row
#define NCHUNK 8               // 1024 columns (256 float4) per chunk
#define NSPLIT 2               // row halves per row-block
#define NCONTRIB (NCHUNK * NSPLIT)  // 16 blocks contribute to each rb

// zero at module load; epilogue re-zeroes after use so graph replays are clean
__device__ float g_sum[RB * CB];
__device__ int   g_done[RB];

// ---------------------------------------------------------------------------
// SINGLE main kernel. Grid (NCHUNK+1, RB, NSPLIT).
//   chunk < NCHUNK  : sum role. Block finds its row-block bounds via two
//                     binary searches on sorted row_ids (L2-hot, overlapped),
//                     streams its 1024-column chunk (unroll-4 LDG.128),
//                     flushes shared acc -> g_sum float atomics, then bumps
//                     g_done[rb]; the 16th block runs the 64-cell MLP for
//                     this rb and self-cleans g_sum/g_done.
//   chunk == NCHUNK : bounds-output role (rb==0: rows, rb==1: cols) writes
//                     the cumsum tail of out. Nothing depends on it ->
//                     hidden under the stream.
//
// Output layout:
//   out[0..4095]      propensity
//   out[4096..4160]   row_cumsum (65, float values)
//   out[4161..4225]   col_cumsum (65, float values)
// ---------------------------------------------------------------------------
__global__ __launch_bounds__(256, 8) void k_sum(const float* __restrict__ X,
                                                const int* __restrict__ row_ids,
                                                const int* __restrict__ col_ids,
                                                const float* __restrict__ W1,
                                                const float* __restrict__ b1,
                                                const float* __restrict__ W2,
                                                const float* __restrict__ b2,
                                                const float* __restrict__ W3,
                                                const float* __restrict__ b3,
                                                float* __restrict__ out) {
    int tid = threadIdx.x;
    int chunk = blockIdx.x;            // 0..NCHUNK (last = bounds role)
    int rb    = blockIdx.y;            // 0..RB-1
    int half  = blockIdx.z;            // 0..NSPLIT-1

    if (chunk == NCHUNK) {
        // -------- bounds-output role: cumsum tail only --------
        if (rb > 1 || half != 0) return;
        const int* __restrict__ ids = (rb == 0) ? row_ids : col_ids;
        float* __restrict__ obase = out + RB * CB + rb * 65;
        if (tid == 0) { obase[0] = 0.f; obase[RB] = (float)NROWS; }
        const int4* __restrict__ p = (const int4*)ids;
        for (int i = tid; i < NROWS / 4; i += 256) {
            int4 v = p[i];
            int j = 4 * i;
            if (j > 0) {
                int prev = ids[j - 1];
                if (v.x != prev) obase[v.x] = (float)j;
            }
            if (v.y != v.x) obase[v.y] = (float)(j + 1);
            if (v.z != v.y) obase[v.z] = (float)(j + 2);
            if (v.w != v.z) obase[v.w] = (float)(j + 3);
        }
        return;
    }

    // -------- sum role --------
    // lower_bound(row_ids, rb) / lower_bound(row_ids, rb+1): uniform across
    // threads (broadcast loads, cache-hot across all blocks).
    int r0, r1;
    {
        int lo = 0, hi = NROWS;
        while (lo < hi) {
            int m = (lo + hi) >> 1;
            if (row_ids[m] < rb) lo = m + 1; else hi = m;
        }
        r0 = lo;
        lo = r0; hi = NROWS;
        while (lo < hi) {
            int m = (lo + hi) >> 1;
            if (row_ids[m] < rb + 1) lo = m + 1; else hi = m;
        }
        r1 = lo;
    }
    int len = r1 - r0;
    int h0 = r0 + (len * half) / NSPLIT;
    int h1 = r0 + (len * (half + 1)) / NSPLIT;

    int c4 = chunk * 256 + tid;                  // float4 column index
    const float4* __restrict__ Xp = (const float4*)X;

    float ax = 0.f, ay = 0.f, az = 0.f, aw = 0.f;
    int base = h0 * T4 + c4;
    int n = h0;
    for (; n + 4 <= h1; n += 4, base += 4 * T4) {
        float4 v0 = Xp[base];
        float4 v1 = Xp[base + T4];
        float4 v2 = Xp[base + 2 * T4];
        float4 v3 = Xp[base + 3 * T4];
        ax += (v0.x + v1.x) + (v2.x + v3.x);
        ay += (v0.y + v1.y) + (v2.y + v3.y);
        az += (v0.z + v1.z) + (v2.z + v3.z);
        aw += (v0.w + v1.w) + (v2.w + v3.w);
    }
    for (; n < h1; n++, base += T4) {
        float4 v = Xp[base];
        ax += v.x; ay += v.y; az += v.z; aw += v.w;
    }

    __shared__ float sacc[CB];
    if (tid < CB) sacc[tid] = 0.f;
    __syncthreads();

    int t = c4 * 4;
    int cb0 = col_ids[t];
    int cb3 = col_ids[t + 3];
    if (cb0 == cb3) {
        atomicAdd(&sacc[cb0], ax + ay + az + aw);
    } else {
        int cb1 = col_ids[t + 1];
        int cb2 = col_ids[t + 2];
        atomicAdd(&sacc[cb0], ax);
        atomicAdd(&sacc[cb1], ay);
        atomicAdd(&sacc[cb2], az);
        atomicAdd(&sacc[cb3], aw);
    }
    __syncthreads();

    // flush to global; only flush threads fence (2 warps)
    if (tid < CB) {
        atomicAdd(&g_sum[rb * CB + tid], sacc[tid]);
        __threadfence();
    }
    __syncthreads();

    __shared__ int is_last;
    if (tid == 0) is_last = (atomicAdd(&g_done[rb], 1) == NCONTRIB - 1);
    __syncthreads();
    if (!is_last) return;

    // -------- per-rb epilogue (cold path, 16th block only) --------
    __threadfence();   // acquire all 16 contributions
    float rcnt = (float)len;
    if (tid < CB) {
        int cb = tid;
        // col block count via two binary searches (L2-hot)
        int lo = 0, hi = TCOLS;
        while (lo < hi) {
            int m = (lo + hi) >> 1;
            if (col_ids[m] < cb) lo = m + 1; else hi = m;
        }
        int cstart = lo;
        hi = TCOLS;
        while (lo < hi) {
            int m = (lo + hi) >> 1;
            if (col_ids[m] < cb + 1) lo = m + 1; else hi = m;
        }
        float ccnt = (float)(lo - cstart);

        float s = __ldcg(&g_sum[rb * CB + cb]);
        g_sum[rb * CB + cb] = 0.f;                 // reset for next replay
        float x = s / (rcnt * ccnt);

        float h1v[3], h2v[3];
#pragma unroll
        for (int j = 0; j < 3; j++) h1v[j] = fmaxf(x * W1[j] + b1[j], 0.f);
#pragma unroll
        for (int j = 0; j < 3; j++) {
            float v = b2[j];
#pragma unroll
            for (int i = 0; i < 3; i++) v += h1v[i] * W2[i * 3 + j];
            h2v[j] = fmaxf(v, 0.f);
        }
        float o = b3[0];
#pragma unroll
        for (int i = 0; i < 3; i++) o += h2v[i] * W3[i];
        out[rb * CB + cb] = 1.f / (1.f + __expf(-o));
    }
    if (tid == 0) g_done[rb] = 0;                  // reset for next replay
}

extern "C" void kernel_launch(void* const* d_in, const int* in_sizes, int n_in,
                              void* d_out, int out_size) {
    const float* X       = (const float*)d_in[0];
    const int*   row_ids = (const int*)d_in[1];
    const int*   col_ids = (const int*)d_in[2];
    const float* W1      = (const float*)d_in[3];
    const float* b1      = (const float*)d_in[4];
    const float* W2      = (const float*)d_in[5];
    const float* b2      = (const float*)d_in[6];
    const float* W3      = (const float*)d_in[7];
    const float* b3      = (const float*)d_in[8];
    float* out = (float*)d_out;

    k_sum<<<dim3(NCHUNK + 1, RB, NSPLIT), 256>>>(X, row_ids, col_ids,
                                                 W1, b1, W2, b2, W3, b3, out);
}

// round 13
// speedup vs baseline: 1.1289x; 1.1289x over previous
#include <cuda_runtime.h>

#define RB 64
#define CB 64
#define NROWS 8192
#define TCOLS 8192
#define T4 (TCOLS / 4)         // 2048 float4 per row
#define NCHUNK 8               // 1024 columns (256 float4) per chunk
#define NSPLIT 2               // row halves per row-block

__device__ int   g_row_start[RB + 1];
__device__ int   g_col_start[CB + 1];
// zero at module load; k_mlp re-zeroes after reading so graph replays are clean
__device__ float g_sum[RB * CB];

// ---------------------------------------------------------------------------
// Kernel 1 (main): grid (NCHUNK+1, RB, NSPLIT).
//   chunk < NCHUNK  : sum role. Bounds found via 2-round cooperative search
//                     (parallel stride-32 probe + warp ballot refine, ~1.2K
//                     cyc vs ~7K for serial binary search), then the clean
//                     unroll-4 LDG.128 stream; shared acc -> g_sum atomics.
//   chunk == NCHUNK : bounds-output role (rb==0: rows, rb==1: cols), writes
//                     cumsums to out and g_*_start. Hidden under the stream.
//
// Output layout:
//   out[0..4095]      propensity (written by k_mlp)
//   out[4096..4160]   row_cumsum (65, float values)
//   out[4161..4225]   col_cumsum (65, float values)
// ---------------------------------------------------------------------------
__global__ __launch_bounds__(256) void k_sum(const float* __restrict__ X,
                                             const int* __restrict__ row_ids,
                                             const int* __restrict__ col_ids,
                                             float* __restrict__ out) {
    int tid = threadIdx.x;
    int chunk = blockIdx.x;            // 0..NCHUNK (last = bounds role)
    int rb    = blockIdx.y;            // 0..RB-1
    int half  = blockIdx.z;            // 0..NSPLIT-1

    if (chunk == NCHUNK) {
        // -------- bounds-output role --------
        if (rb > 1 || half != 0) return;
        const int* __restrict__ ids = (rb == 0) ? row_ids : col_ids;
        int* __restrict__ gstart = (rb == 0) ? g_row_start : g_col_start;
        float* __restrict__ obase = out + RB * CB + rb * 65;
        if (tid == 0) {
            gstart[0] = 0;       obase[0]  = 0.f;
            gstart[RB] = NROWS;  obase[RB] = (float)NROWS;
        }
        const int4* __restrict__ p = (const int4*)ids;
        for (int i = tid; i < NROWS / 4; i += 256) {
            int4 v = p[i];
            int j = 4 * i;
            if (j > 0) {
                int prev = ids[j - 1];
                if (v.x != prev) { gstart[v.x] = j;     obase[v.x] = (float)j; }
            }
            if (v.y != v.x) { gstart[v.y] = j + 1; obase[v.y] = (float)(j + 1); }
            if (v.z != v.y) { gstart[v.z] = j + 2; obase[v.z] = (float)(j + 2); }
            if (v.w != v.z) { gstart[v.w] = j + 3; obase[v.w] = (float)(j + 3); }
        }
        return;
    }

    // -------- sum role: cooperative 2-round lower_bound for rb and rb+1 ----
    __shared__ int sprobe[256];
    __shared__ int sbr[2];     // coarse bracket index t for target rb / rb+1
    __shared__ int sres[2];    // refined r0 / r1

    sprobe[tid] = row_ids[tid * 32];           // one parallel gather round
    if (tid < 2) sbr[tid] = -1;
    __syncthreads();
    // sorted => predicate (sprobe[t] < target) is a true-prefix; find boundary
    {
        int v = sprobe[tid];
        int vn = (tid < 255) ? sprobe[tid + 1] : 0x7fffffff;
        if (v < rb && vn >= rb)         sbr[0] = tid;
        if (v < rb + 1 && vn >= rb + 1) sbr[1] = tid;
    }
    __syncthreads();
    if (tid < 64) {                            // warps 0,1: refine each target
        int w = tid >> 5;                      // 0 -> rb, 1 -> rb+1
        int lane = tid & 31;
        int target = rb + w;
        int t = sbr[w];
        int start = (t < 0) ? 0 : t * 32 + 1;  // lower_bound lies in [start, start+32]
        int pos = start + lane;
        int v = (pos < NROWS) ? row_ids[pos] : 0x7fffffff;
        unsigned m = __ballot_sync(0xffffffffu, v < target);
        if (lane == 0) sres[w] = start + __popc(m);
    }
    __syncthreads();
    int r0 = sres[0];
    int r1 = sres[1];

    int len = r1 - r0;
    int h0 = r0 + (len * half) / NSPLIT;
    int h1 = r0 + (len * (half + 1)) / NSPLIT;

    int c4 = chunk * 256 + tid;                  // float4 column index
    const float4* __restrict__ Xp = (const float4*)X;

    float ax = 0.f, ay = 0.f, az = 0.f, aw = 0.f;
    int base = h0 * T4 + c4;
    int n = h0;
    for (; n + 4 <= h1; n += 4, base += 4 * T4) {
        float4 v0 = Xp[base];
        float4 v1 = Xp[base + T4];
        float4 v2 = Xp[base + 2 * T4];
        float4 v3 = Xp[base + 3 * T4];
        ax += (v0.x + v1.x) + (v2.x + v3.x);
        ay += (v0.y + v1.y) + (v2.y + v3.y);
        az += (v0.z + v1.z) + (v2.z + v3.z);
        aw += (v0.w + v1.w) + (v2.w + v3.w);
    }
    for (; n < h1; n++, base += T4) {
        float4 v = Xp[base];
        ax += v.x; ay += v.y; az += v.z; aw += v.w;
    }

    __shared__ float sacc[CB];
    if (tid < CB) sacc[tid] = 0.f;
    __syncthreads();

    int t4i = c4 * 4;
    int cb0 = col_ids[t4i];
    int cb3 = col_ids[t4i + 3];
    if (cb0 == cb3) {
        atomicAdd(&sacc[cb0], ax + ay + az + aw);
    } else {
        int cb1 = col_ids[t4i + 1];
        int cb2 = col_ids[t4i + 2];
        atomicAdd(&sacc[cb0], ax);
        atomicAdd(&sacc[cb1], ay);
        atomicAdd(&sacc[cb2], az);
        atomicAdd(&sacc[cb3], aw);
    }
    __syncthreads();
    if (tid < CB) atomicAdd(&g_sum[rb * CB + tid], sacc[tid]);
}

// ---------------------------------------------------------------------------
// Kernel 2: block mean -> 1->3->3->1 relu MLP -> sigmoid. Re-zeroes g_sum
// after reading so the next graph replay starts clean.
// ---------------------------------------------------------------------------
__global__ void k_mlp(const float* __restrict__ W1, const float* __restrict__ b1,
                      const float* __restrict__ W2, const float* __restrict__ b2,
                      const float* __restrict__ W3, const float* __restrict__ b3,
                      float* __restrict__ out) {
    int idx = blockIdx.x * blockDim.x + threadIdx.x;
    if (idx >= RB * CB) return;
    int rb = idx / CB;
    int cb = idx % CB;
    float s = g_sum[idx];
    g_sum[idx] = 0.f;   // reset for next call
    float rcnt = (float)(g_row_start[rb + 1] - g_row_start[rb]);
    float ccnt = (float)(g_col_start[cb + 1] - g_col_start[cb]);
    float x = s / (rcnt * ccnt);

    float h1v[3], h2v[3];
#pragma unroll
    for (int j = 0; j < 3; j++) h1v[j] = fmaxf(x * W1[j] + b1[j], 0.f);
#pragma unroll
    for (int j = 0; j < 3; j++) {
        float v = b2[j];
#pragma unroll
        for (int i = 0; i < 3; i++) v += h1v[i] * W2[i * 3 + j];
        h2v[j] = fmaxf(v, 0.f);
    }
    float o = b3[0];
#pragma unroll
    for (int i = 0; i < 3; i++) o += h2v[i] * W3[i];
    out[idx] = 1.f / (1.f + __expf(-o));
}

extern "C" void kernel_launch(void* const* d_in, const int* in_sizes, int n_in,
                              void* d_out, int out_size) {
    const float* X       = (const float*)d_in[0];
    const int*   row_ids = (const int*)d_in[1];
    const int*   col_ids = (const int*)d_in[2];
    const float* W1      = (const float*)d_in[3];
    const float* b1      = (const float*)d_in[4];
    const float* W2      = (const float*)d_in[5];
    const float* b2      = (const float*)d_in[6];
    const float* W3      = (const float*)d_in[7];
    const float* b3      = (const float*)d_in[8];
    float* out = (float*)d_out;

    k_sum<<<dim3(NCHUNK + 1, RB, NSPLIT), 256>>>(X, row_ids, col_ids, out);
    k_mlp<<<32, 128>>>(W1, b1, W2, b2, W3, b3, out);
}